// round 17
// baseline (speedup 1.0000x reference)
#include <cuda_runtime.h>
#include <math.h>

#define L 512
#define NCON 20
#define INV_TEMP (1.0f / 0.07f)
#define MAXROWS 32768
#define SD_BLOCKS 592   // 4 blocks/SM on 148 SMs
#define SD_THREADS 256
#define WPB (SD_THREADS / 32)
#define FULLMASK 0xffffffffu

// scratch (device globals; no allocation allowed)
// cnt arrays: zero-initialized at load; reset-on-consume in the row kernel
// keeps them all-zero at the start of every replay.
__device__ int   g_cnt0[MAXROWS];        // histogram of sz_idx
__device__ int   g_cnt1[MAXROWS];        // histogram of nsz_idx
__device__ float g_pB[SD_BLOCKS];        // per-block partials
__device__ unsigned int g_fin = 0;       // finalize counter (reset by last block)

// ---------------------------------------------------------------------------
// Kernel 1: index histograms (deterministic int atomics).
// ---------------------------------------------------------------------------
__global__ void hist_kernel(const int* __restrict__ sz_idx, int Ns,
                            const int* __restrict__ nsz_idx, int Nn, int Bs) {
    int b = blockIdx.x;
    int branch = (b >= Bs) ? 1 : 0;
    int i = (branch ? (b - Bs) : b) * (int)blockDim.x + threadIdx.x;
    if (branch) {
        if (i < Nn) atomicAdd(&g_cnt1[nsz_idx[i]], 1);
    } else {
        if (i < Ns) atomicAdd(&g_cnt0[sz_idx[i]], 1);
    }
}

// ---------------------------------------------------------------------------
// Kernel 2: COMBINED-branch row pass with ballot skip + finalize.
// Every unique sampled row is read exactly ONCE (~41MB vs R12's 64MB).
// Warp w owns rpw contiguous rows; counts for both branches load in one
// parallel shot (reset-on-consume, off the dependent chain); only rows with
// c0|c1 != 0 are processed, using R6's proven 32-reg dual-branch body:
//   acc += c0*invNs*(log den0 - d0*invn/tau) + c1*invNn*(log den1 - d1*invn/tau)
// Deterministic: fixed chunk map, fixed ballot order, fixed trees,
// fixed-order last-block finalize.
// ---------------------------------------------------------------------------
__global__ void __launch_bounds__(SD_THREADS)
rowpass_kernel(const float* __restrict__ hg, int nrows,
               const float* __restrict__ corr,
               const float* __restrict__ all_emb,
               const int* __restrict__ Psz, int nPsz,
               const int* __restrict__ Pnsz, int nPnsz,
               int rpw, float invNs, float invNn,
               float* __restrict__ out) {
    __shared__ float se0[L];
    __shared__ float se1[L];
    __shared__ int sp[2][16];
    __shared__ float sw[WPB];
    __shared__ float sh[SD_THREADS];
    __shared__ bool is_last;

    int tid = threadIdx.x;

    if (tid < nPsz)                    sp[0][tid]      = Psz[tid];
    if (tid >= 32 && tid - 32 < nPnsz) sp[1][tid - 32] = Pnsz[tid - 32];
    __syncthreads();

    // exclusion bitmasks (uniform)
    unsigned int mask0 = 0u, mask1 = 0u;
    for (int j = 0; j < nPsz; j++)  mask0 |= 1u << sp[0][j];
    for (int j = 0; j < nPnsz; j++) mask1 |= 1u << sp[1][j];

    // build both ebars into smem (10 L2-hot concept rows, overlapped)
    for (int t = tid; t < L; t += SD_THREADS) {
        float s0 = 0.0f, s1 = 0.0f;
        for (int j = 0; j < nPsz; j++)  s0 += all_emb[sp[0][j] * L + t];
        for (int j = 0; j < nPnsz; j++) s1 += all_emb[sp[1][j] * L + t];
        se0[t] = s0 / (float)nPsz;
        se1[t] = s1 / (float)nPnsz;
    }
    __syncthreads();

    int lane = tid & 31;
    int wib  = tid >> 5;
    int wg   = blockIdx.x * WPB + wib;   // global warp id

    const float4* e0p = reinterpret_cast<const float4*>(se0);
    const float4* e1p = reinterpret_cast<const float4*>(se1);
    bool act = lane < NCON;
    float w0m = (act && !((mask0 >> lane) & 1u)) ? 1.0f : 0.0f;
    float w1m = (act && !((mask1 >> lane) & 1u)) ? 1.0f : 0.0f;

    float acc = 0.0f;
    int row0 = wg * rpw;
    if (row0 < nrows) {
        int nmine = nrows - row0;
        if (nmine > rpw) nmine = rpw;

        // parallel count loads for both branches (off the dependent chain),
        // reset-on-consume for the next replay
        int c0l = (lane < nmine) ? g_cnt0[row0 + lane] : 0;
        int c1l = (lane < nmine) ? g_cnt1[row0 + lane] : 0;
        if (c0l) g_cnt0[row0 + lane] = 0;
        if (c1l) g_cnt1[row0 + lane] = 0;
        unsigned int bal = __ballot_sync(FULLMASK, (c0l | c1l) != 0);

        while (bal) {
            int b = __ffs(bal) - 1;
            bal &= bal - 1;
            int row = row0 + b;
            float c0 = (float)__shfl_sync(FULLMASK, c0l, b);
            float c1 = (float)__shfl_sync(FULLMASK, c1l, b);

            // denominators: lanes 0..19 handle one concept each
            float e = act ? __expf(corr[row * NCON + lane] * INV_TEMP) : 0.0f;
            float den0 = e * w0m;
            float den1 = e * w1m;

            const float4* rp = reinterpret_cast<const float4*>(hg + (size_t)row * L);
            float ss = 0.0f, d0 = 0.0f, d1 = 0.0f;
#pragma unroll
            for (int it = 0; it < 4; it++) {
                int idx = it * 32 + lane;
                float4 v  = rp[idx];
                float4 e0 = e0p[idx];
                float4 e1 = e1p[idx];
                ss = fmaf(v.x, v.x, fmaf(v.y, v.y, fmaf(v.z, v.z, fmaf(v.w, v.w, ss))));
                d0 = fmaf(v.x, e0.x, fmaf(v.y, e0.y, fmaf(v.z, e0.z, fmaf(v.w, e0.w, d0))));
                d1 = fmaf(v.x, e1.x, fmaf(v.y, e1.y, fmaf(v.z, e1.z, fmaf(v.w, e1.w, d1))));
            }
#pragma unroll
            for (int o = 16; o > 0; o >>= 1) {
                ss   += __shfl_xor_sync(FULLMASK, ss, o);
                d0   += __shfl_xor_sync(FULLMASK, d0, o);
                d1   += __shfl_xor_sync(FULLMASK, d1, o);
                den0 += __shfl_xor_sync(FULLMASK, den0, o);
                den1 += __shfl_xor_sync(FULLMASK, den1, o);
            }
            if (lane == 0) {
                float invn = 1.0f / fmaxf(sqrtf(ss), 1e-12f);
                float dscale = invn * INV_TEMP;
                if (c0 != 0.0f)
                    acc += c0 * invNs * (__logf(den0) - d0 * dscale);
                if (c1 != 0.0f)
                    acc += c1 * invNn * (__logf(den1) - d1 * dscale);
            }
        }
    }

    // block partial + last-block fixed-order finalize
    if (lane == 0) sw[wib] = acc;
    __syncthreads();
    if (tid == 0) {
        float s = 0.0f;
#pragma unroll
        for (int k = 0; k < WPB; k++) s += sw[k];
        g_pB[blockIdx.x] = s;
        __threadfence();
        is_last = (atomicAdd(&g_fin, 1u) == gridDim.x - 1);
    }
    __syncthreads();

    if (is_last) {
        __threadfence();  // see all blocks' partials
        float a = 0.0f;
        for (int j = tid; j < SD_BLOCKS; j += SD_THREADS) a += g_pB[j];  // fixed order
        sh[tid] = a;
        __syncthreads();
        for (int s = 128; s > 0; s >>= 1) {
            if (tid < s) sh[tid] += sh[tid + s];
            __syncthreads();
        }
        if (tid == 0) { out[0] = sh[0]; g_fin = 0u; }
    }
}

extern "C" void kernel_launch(void* const* d_in, const int* in_sizes, int n_in,
                              void* d_out, int out_size) {
    const float* hg       = (const float*)d_in[0];
    const float* corr     = (const float*)d_in[1];
    const float* all_emb  = (const float*)d_in[2];
    const int*   sz_idx   = (const int*)d_in[3];
    const int*   nsz_idx  = (const int*)d_in[4];
    const int*   Psz_idx  = (const int*)d_in[5];
    const int*   Pnsz_idx = (const int*)d_in[6];
    float* out = (float*)d_out;

    int nrows = in_sizes[0] / L;          // 32768
    int Ns    = in_sizes[3];
    int Nn    = in_sizes[4];
    int nPsz  = in_sizes[5];
    int nPnsz = in_sizes[6];

    int Bs = (Ns + 255) / 256;
    int Bn = (Nn + 255) / 256;
    hist_kernel<<<Bs + Bn, 256>>>(sz_idx, Ns, nsz_idx, Nn, Bs);

    int nwarps = SD_BLOCKS * WPB;                   // 4736 warps
    int rpw = (nrows + nwarps - 1) / nwarps;        // 7 contiguous rows/warp
    if (rpw > 32) rpw = 32;                         // ballot width safety

    rowpass_kernel<<<SD_BLOCKS, SD_THREADS>>>(hg, nrows, corr, all_emb,
                                              Psz_idx, nPsz, Pnsz_idx, nPnsz,
                                              rpw, 1.0f / (float)Ns, 1.0f / (float)Nn,
                                              out);
}